// round 10
// baseline (speedup 1.0000x reference)
#include <cuda_runtime.h>
#include <cuda_fp16.h>
#include <cstdint>

// Problem constants (fixed by the reference)
#define NN   50000
#define EE   800000
#define DD   128
#define HH   8
#define CC   16
#define EDD  64
#define LL   3

// ---------------- scratch (static device globals; no allocation) -------------
__device__ float  g_q  [NN * DD];
__device__ float  g_k  [NN * DD];
__device__ float  g_v  [NN * DD];
__device__ float  g_out[NN * DD];     // skip (x@Ws+bs), then final pre-BN out
__device__ __half g_xh [NN * DD];     // x split hi
__device__ __half g_xl [NN * DD];     // x split lo
__device__ __half g_ea16[(size_t)EE * EDD];    // edge_attr fp16, CSR-permuted
__device__ __half g_wet [DD * EDD];            // We^T fp16 [ch=128][k=64]
__device__ __half g_wallh[512 * DD];           // [Wq|Wk|Wv|Ws]^T hi
__device__ __half g_walll[512 * DD];           // lo part
__device__ float  g_ball [512];                // [bq|bk|bv|bs]
__device__ float  g_alpha[(size_t)EE * HH];    // raw scores (CSR order)
__device__ double g_sums[2 * DD];
__device__ float2 g_ab  [DD];
// CSR (dst-sorted edge order; edge_index is launch-constant)
__device__ int    g_deg   [NN];
__device__ int    g_cursor[NN];
__device__ int    g_rowptr[NN + 1];
__device__ int    g_eord  [EE];
__device__ int    g_srcp  [EE];      // src per CSR position
__device__ int    g_bsums [256];

// ---------------- helpers ----------------------------------------------------
__device__ __forceinline__ uint32_t smem_u32(const void* p) {
    uint32_t a;
    asm("{ .reg .u64 t; cvta.to.shared.u64 t, %1; cvt.u32.u64 %0, t; }" : "=r"(a) : "l"(p));
    return a;
}
__device__ __forceinline__ uint32_t sw64(uint32_t off) { return off ^ ((off >> 3) & 0x30); }

__device__ __forceinline__ void ldmatrix_x4(uint32_t* r, uint32_t addr) {
    asm volatile("ldmatrix.sync.aligned.m8n8.x4.shared.b16 {%0,%1,%2,%3}, [%4];"
                 : "=r"(r[0]), "=r"(r[1]), "=r"(r[2]), "=r"(r[3]) : "r"(addr));
}
__device__ __forceinline__ void mma16816(float* c, const uint32_t* a, const uint32_t* b) {
    asm volatile("mma.sync.aligned.m16n8k16.row.col.f32.f16.f16.f32 "
                 "{%0,%1,%2,%3}, {%4,%5,%6,%7}, {%8,%9}, {%0,%1,%2,%3};"
                 : "+f"(c[0]), "+f"(c[1]), "+f"(c[2]), "+f"(c[3])
                 : "r"(a[0]), "r"(a[1]), "r"(a[2]), "r"(a[3]), "r"(b[0]), "r"(b[1]));
}

// ---------------- CSR build (once per launch) ----------------------------------
__global__ void csr_zero() {
    int i = blockIdx.x * blockDim.x + threadIdx.x;
    if (i < NN) { g_deg[i] = 0; g_cursor[i] = 0; }
}
__global__ void csr_hist(const int* __restrict__ ei) {
    int e = blockIdx.x * blockDim.x + threadIdx.x;
    if (e < EE) atomicAdd(&g_deg[ei[EE + e]], 1);
}
__global__ void csr_scan1() {
    __shared__ int s[256];
    int t = threadIdx.x;
    int i = blockIdx.x * 256 + t;
    int v = (i < NN) ? g_deg[i] : 0;
    s[t] = v;
    __syncthreads();
    for (int st = 1; st < 256; st <<= 1) {
        int x = (t >= st) ? s[t - st] : 0;
        __syncthreads();
        if (t >= st) s[t] += x;
        __syncthreads();
    }
    if (i < NN) g_rowptr[i] = s[t] - v;
    if (t == 255) g_bsums[blockIdx.x] = s[255];
}
__global__ void csr_scan2(int nblocks) {
    if (threadIdx.x == 0 && blockIdx.x == 0) {
        int run = 0;
        for (int b = 0; b < nblocks; b++) { int x = g_bsums[b]; g_bsums[b] = run; run += x; }
    }
}
__global__ void csr_scan3() {
    int i = blockIdx.x * blockDim.x + threadIdx.x;
    if (i < NN) g_rowptr[i] += g_bsums[i >> 8];
    if (i == 0) g_rowptr[NN] = EE;
}
__global__ void csr_fill(const int* __restrict__ ei) {
    int e = blockIdx.x * blockDim.x + threadIdx.x;
    if (e >= EE) return;
    int d = ei[EE + e];
    int pos = g_rowptr[d] + atomicAdd(&g_cursor[d], 1);
    g_eord[pos] = e;
}
__global__ void perm_idx_kernel(const int* __restrict__ ei) {
    int p = blockIdx.x * blockDim.x + threadIdx.x;
    if (p >= EE) return;
    g_srcp[p] = ei[g_eord[p]];
}
// edge_attr -> fp16, permuted into CSR order
__global__ void conv_ea_perm(const float* __restrict__ ea) {
    int i = blockIdx.x * blockDim.x + threadIdx.x;   // over 4-float units
    int p = i >> 4;
    if (p >= EE) return;
    int off = (i & 15) * 4;
    int eid = g_eord[p];
    float4 f = *(const float4*)(ea + (size_t)eid * EDD + off);
    __half2 h01 = __floats2half2_rn(f.x, f.y);
    __half2 h23 = __floats2half2_rn(f.z, f.w);
    uint2 pk;
    pk.x = *(const unsigned*)&h01;
    pk.y = *(const unsigned*)&h23;
    *(uint2*)(g_ea16 + (size_t)p * EDD + off) = pk;
}

// ---------------- one-time / per-layer prep ------------------------------------
__global__ void xsplit0_kernel(const float* __restrict__ x) {
    int i = blockIdx.x * blockDim.x + threadIdx.x;
    if (i >= NN * DD) return;
    float f = x[i];
    __half h = __float2half(f);
    g_xh[i] = h;
    g_xl[i] = __float2half(f - __half2float(h));
}

__global__ void wet_kernel(const float* __restrict__ We) {   // -> g_wet[ch][k] = We[k][ch]
    int i = blockIdx.x * blockDim.x + threadIdx.x;
    if (i >= DD * EDD) return;
    int n = i / EDD, k = i % EDD;
    g_wet[i] = __float2half(We[k * DD + n]);
}

__global__ void wall_prep_kernel(const float* __restrict__ Wq, const float* __restrict__ Wk,
                                 const float* __restrict__ Wv, const float* __restrict__ Ws,
                                 const float* __restrict__ bq, const float* __restrict__ bk,
                                 const float* __restrict__ bv, const float* __restrict__ bs) {
    int i = blockIdx.x * blockDim.x + threadIdx.x;
    if (i >= 512 * DD) return;
    int ng = i / DD;
    int k  = i % DD;
    int mtx = ng >> 7, nloc = ng & 127;
    const float* W = (mtx == 0) ? Wq : (mtx == 1) ? Wk : (mtx == 2) ? Wv : Ws;
    float w = W[k * DD + nloc];
    __half h = __float2half(w);
    g_wallh[i] = h;
    g_walll[i] = __float2half(w - __half2float(h));
    if (i < 512) {
        int m2 = i >> 7, l2 = i & 127;
        const float* b = (m2 == 0) ? bq : (m2 == 1) ? bk : (m2 == 2) ? bv : bs;
        g_ball[i] = b[l2];
    }
}

__global__ void init_kernel() {
    int i = threadIdx.x;
    if (i < 2 * DD) g_sums[i] = 0.0;
}

// ------------- fused node GEMM (split-fp16 HMMA): [q|k|v|skip] -----------------
__global__ void __launch_bounds__(256, 2)
node_gemm_mma(float* __restrict__ oq, float* __restrict__ okk,
              float* __restrict__ ov, float* __restrict__ os) {
    __shared__ __align__(128) __half sAh[128 * 32];
    __shared__ __align__(128) __half sAl[128 * 32];
    __shared__ __align__(128) __half sBh[128 * 32];
    __shared__ __align__(128) __half sBl[128 * 32];
    __shared__ float sbias[128];

    const int tid  = threadIdx.x;
    const int wid  = tid >> 5;
    const int lane = tid & 31;
    const int ntile = blockIdx.x & 3;
    const int mbase = (blockIdx.x >> 2) * 128;

    if (tid < 128) sbias[tid] = g_ball[ntile * 128 + tid];

    float acc[16][4];
#pragma unroll
    for (int i = 0; i < 16; i++)
#pragma unroll
        for (int j = 0; j < 4; j++) acc[i][j] = 0.0f;

    const uint32_t sAhu = smem_u32(sAh);
    const uint32_t sAlu = smem_u32(sAl);
    const uint32_t sBhu = smem_u32(sBh);
    const uint32_t sBlu = smem_u32(sBl);
    const int mrow = wid * 16;

    for (int kc = 0; kc < 4; kc++) {
#pragma unroll
        for (int i = 0; i < 2; i++) {
            int idx = i * 256 + tid;
            int row = idx >> 2, unit = idx & 3;
            int grow = mbase + row;
            uint4 vh = make_uint4(0, 0, 0, 0), vl = make_uint4(0, 0, 0, 0);
            if (grow < NN) {
                size_t g = (size_t)grow * DD + kc * 32 + unit * 8;
                vh = *(const uint4*)(g_xh + g);
                vl = *(const uint4*)(g_xl + g);
            }
            *(uint4*)((char*)sAh + sw64(idx * 16)) = vh;
            *(uint4*)((char*)sAl + sw64(idx * 16)) = vl;
        }
#pragma unroll
        for (int i = 0; i < 2; i++) {
            int idx = i * 256 + tid;
            int row = idx >> 2, unit = idx & 3;
            size_t g = (size_t)(ntile * 128 + row) * DD + kc * 32 + unit * 8;
            *(uint4*)((char*)sBh + sw64(idx * 16)) = *(const uint4*)(g_wallh + g);
            *(uint4*)((char*)sBl + sw64(idx * 16)) = *(const uint4*)(g_walll + g);
        }
        __syncthreads();

#pragma unroll
        for (int t = 0; t < 2; t++) {
            uint32_t ah[4], al[4];
            uint32_t aoff = (uint32_t)(mrow + (lane & 15)) * 64 + t * 32 + ((lane >> 4) * 16);
            ldmatrix_x4(ah, sAhu + sw64(aoff));
            ldmatrix_x4(al, sAlu + sw64(aoff));
#pragma unroll
            for (int np = 0; np < 8; np++) {
                int mtx = lane >> 3;
                uint32_t boff = (uint32_t)(np * 16 + ((mtx >> 1) * 8) + (lane & 7)) * 64
                              + t * 32 + ((mtx & 1) * 16);
                uint32_t bh[4], bl[4];
                ldmatrix_x4(bh, sBhu + sw64(boff));
                ldmatrix_x4(bl, sBlu + sw64(boff));
                mma16816(acc[2 * np],     ah, bh);
                mma16816(acc[2 * np],     ah, bl);
                mma16816(acc[2 * np],     al, bh);
                mma16816(acc[2 * np + 1], ah, bh + 2);
                mma16816(acc[2 * np + 1], ah, bl + 2);
                mma16816(acc[2 * np + 1], al, bh + 2);
            }
        }
        __syncthreads();
    }

    float* dst = (ntile == 0) ? oq : (ntile == 1) ? okk : (ntile == 2) ? ov : os;
    const int r0 = mbase + mrow + (lane >> 2);
    const int cq = (lane & 3) * 2;
#pragma unroll
    for (int nt = 0; nt < 16; nt++) {
        int n = nt * 8 + cq;
        float b0 = sbias[n], b1 = sbias[n + 1];
        if (r0 < NN)
            *(float2*)(dst + (size_t)r0 * DD + n) = make_float2(acc[nt][0] + b0, acc[nt][1] + b1);
        if (r0 + 8 < NN)
            *(float2*)(dst + (size_t)(r0 + 8) * DD + n) = make_float2(acc[nt][2] + b0, acc[nt][3] + b1);
    }
}

// ---------------- per-node alpha: qproj in smem, no e materialization -----------
// alpha[p,h] = ( q·k + ea_p·qproj[:,h] + q_h·be_h ) / 4
__global__ void __launch_bounds__(128)
alpha_node_kernel(const float* __restrict__ be) {
    const int n   = blockIdx.x;
    const int tid = threadIdx.x;
    const int start = g_rowptr[n], end = g_rowptr[n + 1];
    if (start == end) return;

    __shared__ __align__(16) float sq[128];
    __shared__ float sproj[512];     // [k*8 + h]
    __shared__ float sqbe[8];
    __shared__ __align__(16) __half sea[16 * 64];

    sq[tid] = g_q[(size_t)n * DD + tid];
    __syncthreads();

    // qproj[k,h] = sum_c We[k, h*16+c] * q[h*16+c]; thread owns h=tid>>4, k=k0..k0+3
    {
        const int hh = tid >> 4;
        const int k0 = (tid & 15) * 4;
        float s0 = 0.f, s1 = 0.f, s2 = 0.f, s3 = 0.f;
#pragma unroll
        for (int c = 0; c < 16; c++) {
            const __half2* wr = (const __half2*)(g_wet + (size_t)(hh * 16 + c) * 64 + k0);
            float2 w01 = __half22float2(wr[0]);
            float2 w23 = __half22float2(wr[1]);
            float qv = sq[hh * 16 + c];
            s0 += w01.x * qv; s1 += w01.y * qv;
            s2 += w23.x * qv; s3 += w23.y * qv;
        }
        sproj[(k0 + 0) * 8 + hh] = s0;
        sproj[(k0 + 1) * 8 + hh] = s1;
        sproj[(k0 + 2) * 8 + hh] = s2;
        sproj[(k0 + 3) * 8 + hh] = s3;
    }
    if (tid < 8) {
        float s = 0.f;
#pragma unroll
        for (int c = 0; c < 16; c++)
            s += sq[tid * 16 + c] * be[tid * 16 + c];
        sqbe[tid] = s;
    }
    __syncthreads();

    const int i0 = tid >> 3, h8 = tid & 7;
    for (int base = start; base < end; base += 16) {
        int cnt = min(16, end - base);
        if (tid < cnt * 8)
            ((uint4*)sea)[tid] = ((const uint4*)(g_ea16 + (size_t)base * EDD))[tid];
        __syncthreads();
        if (i0 < cnt) {
            int src = g_srcp[base + i0];
            const float4* kr = (const float4*)(g_k + (size_t)src * DD + h8 * 16);
            const float4* qr = (const float4*)(sq + h8 * 16);
            float s = sqbe[h8];
#pragma unroll
            for (int c = 0; c < 4; c++) {
                float4 kq = kr[c], qq = qr[c];
                s += qq.x * kq.x + qq.y * kq.y + qq.z * kq.z + qq.w * kq.w;
            }
            const __half2* ee = (const __half2*)(sea + i0 * 64);
#pragma unroll
            for (int kk = 0; kk < 32; kk++) {
                float2 ev = __half22float2(ee[kk]);
                s += ev.x * sproj[(2 * kk) * 8 + h8] + ev.y * sproj[(2 * kk + 1) * 8 + h8];
            }
            g_alpha[(size_t)(base + i0) * HH + h8] = s * 0.25f;
        }
        __syncthreads();
    }
}

// ---- per-node gather: softmax + Sv + S-accumulate + We-project + skip add ------
// msg[ch] = ( Sv[ch] + S[h,:]*We[:,ch] + den_h*be[ch] ) / (den_h+1e-16)
__global__ void __launch_bounds__(128)
gather_kernel(const float* __restrict__ be) {
    const int n   = blockIdx.x;
    const int tid = threadIdx.x;
    const int start = g_rowptr[n], end = g_rowptr[n + 1];
    if (start == end) return;
    const int i0 = tid >> 3, h8 = tid & 7, hch = tid >> 4;
    const int k0 = (tid & 15) * 4;

    __shared__ float smax[128];
    __shared__ float sex[16][8];
    __shared__ int   ssrc[16];
    __shared__ float sden[8];
    __shared__ float sS[512];                 // [h*64 + k]
    __shared__ __align__(16) __half sea[16 * 64];

    float lmax = -3.0e38f;
    for (int p = start + i0; p < end; p += 16)
        lmax = fmaxf(lmax, g_alpha[(size_t)p * HH + h8]);
    smax[tid] = lmax;
    __syncthreads();
#pragma unroll
    for (int s = 64; s >= 8; s >>= 1) {
        if (tid < s) smax[tid] = fmaxf(smax[tid], smax[tid + s]);
        __syncthreads();
    }
    const float amax = smax[h8];

    float msgv = 0.0f, den = 0.0f;
    float S0 = 0.f, S1 = 0.f, S2 = 0.f, S3 = 0.f;
    for (int base = start; base < end; base += 16) {
        int cnt = min(16, end - base);
        if (tid < cnt) ssrc[tid] = g_srcp[base + tid];
        if (i0 < cnt)
            sex[i0][h8] = __expf(g_alpha[(size_t)(base + i0) * HH + h8] - amax);
        if (tid < cnt * 8)
            ((uint4*)sea)[tid] = ((const uint4*)(g_ea16 + (size_t)base * EDD))[tid];
        __syncthreads();
#pragma unroll 4
        for (int i = 0; i < cnt; i++) {
            float exv = sex[i][hch];
            msgv += exv * g_v[(size_t)ssrc[i] * DD + tid];
            const __half2* ep = (const __half2*)(sea + i * 64 + k0);
            float2 e01 = __half22float2(ep[0]);
            float2 e23 = __half22float2(ep[1]);
            S0 += exv * e01.x; S1 += exv * e01.y;
            S2 += exv * e23.x; S3 += exv * e23.y;
        }
        if (tid < 8) {
            float s = 0.0f;
            for (int i = 0; i < cnt; i++) s += sex[i][tid];
            den += s;
        }
        __syncthreads();
    }
    sS[tid * 4 + 0] = S0;     // == sS[hch*64 + k0 + j]
    sS[tid * 4 + 1] = S1;
    sS[tid * 4 + 2] = S2;
    sS[tid * 4 + 3] = S3;
    if (tid < 8) sden[tid] = den;
    __syncthreads();

    const float dn = sden[hch];
    const __half2* wc = (const __half2*)(g_wet + (size_t)tid * 64);
    const float* Sp = sS + hch * 64;
    float me = 0.f;
#pragma unroll
    for (int kk = 0; kk < 32; kk++) {
        float2 w = __half22float2(wc[kk]);
        me += Sp[2 * kk] * w.x + Sp[2 * kk + 1] * w.y;
    }
    float o = (msgv + me + dn * be[tid]) / (dn + 1e-16f) + g_out[(size_t)n * DD + tid];
    g_out[(size_t)n * DD + tid] = o;
}

// ---- BN column sums (fp64) -----------------------------------------------------
__global__ void bn_sum_kernel() {
    int ch = threadIdx.x;
    double s = 0.0, s2 = 0.0;
    for (int r = blockIdx.x; r < NN; r += gridDim.x) {
        float v = g_out[(size_t)r * DD + ch];
        s  += (double)v;
        s2 += (double)v * (double)v;
    }
    atomicAdd(&g_sums[ch], s);
    atomicAdd(&g_sums[DD + ch], s2);
}

__global__ void bn_fin_kernel(const float* __restrict__ gamma,
                              const float* __restrict__ beta) {
    int ch = threadIdx.x;
    double mu  = g_sums[ch] / (double)NN;
    double var = g_sums[DD + ch] / (double)NN - mu * mu;
    double rs  = 1.0 / sqrt(var + 1e-5);
    float a = gamma[ch] * (float)rs;
    float b = beta[ch] - (float)mu * a;
    g_ab[ch] = make_float2(a, b);
}

__global__ void bn_apply_kernel(float* __restrict__ xo, int write_f32) {
    int idx = blockIdx.x * blockDim.x + threadIdx.x;
    if (idx >= NN * DD) return;
    int ch = idx & (DD - 1);
    float2 c = g_ab[ch];
    float y = g_out[idx] * c.x + c.y;
    y = (y >= 0.0f) ? y : 0.01f * y;
    __half h = __float2half(y);
    g_xh[idx] = h;
    g_xl[idx] = __float2half(y - __half2float(h));
    if (write_f32) xo[idx] = y;
}

// ---------------- driver -------------------------------------------------------
extern "C" void kernel_launch(void* const* d_in, const int* in_sizes, int n_in,
                              void* d_out, int out_size) {
    const float* x     = (const float*)d_in[0];
    const int*   ei    = (const int*)  d_in[1];
    const float* ea    = (const float*)d_in[2];
    const float* Wq    = (const float*)d_in[3];
    const float* bq    = (const float*)d_in[4];
    const float* Wk    = (const float*)d_in[5];
    const float* bk    = (const float*)d_in[6];
    const float* Wv    = (const float*)d_in[7];
    const float* bv    = (const float*)d_in[8];
    const float* We    = (const float*)d_in[9];
    const float* be    = (const float*)d_in[10];
    const float* Ws    = (const float*)d_in[11];
    const float* bs    = (const float*)d_in[12];
    const float* gamma = (const float*)d_in[13];
    const float* beta  = (const float*)d_in[14];
    float* out = (float*)d_out;

    float *q, *k, *v, *ob;
    cudaGetSymbolAddress((void**)&q,  g_q);
    cudaGetSymbolAddress((void**)&k,  g_k);
    cudaGetSymbolAddress((void**)&v,  g_v);
    cudaGetSymbolAddress((void**)&ob, g_out);

    const int nodeGemmBlocks = ((NN + 127) / 128) * 4;  // 1564
    const int nodeB          = (NN + 255) / 256;        // 196

    // one-time per launch: CSR build, permutation, conversions
    csr_zero <<<nodeB, 256>>>();
    csr_hist <<<(EE + 255) / 256, 256>>>(ei);
    csr_scan1<<<nodeB, 256>>>();
    csr_scan2<<<1, 32>>>(nodeB);
    csr_scan3<<<nodeB, 256>>>();
    csr_fill <<<(EE + 255) / 256, 256>>>(ei);
    perm_idx_kernel<<<(EE + 255) / 256, 256>>>(ei);
    conv_ea_perm<<<(int)(((size_t)EE * 16 + 255) / 256), 256>>>(ea);
    xsplit0_kernel<<<(NN * DD + 255) / 256, 256>>>(x);

    for (int l = 0; l < LL; l++) {
        init_kernel<<<1, 256>>>();
        wet_kernel <<<(DD * EDD + 255) / 256, 256>>>(We + (size_t)l * EDD * DD);
        wall_prep_kernel<<<(512 * DD + 255) / 256, 256>>>(
            Wq + (size_t)l * DD * DD, Wk + (size_t)l * DD * DD,
            Wv + (size_t)l * DD * DD, Ws + (size_t)l * DD * DD,
            bq + l * DD, bk + l * DD, bv + l * DD, bs + l * DD);

        node_gemm_mma<<<nodeGemmBlocks, 256>>>(q, k, v, ob);

        alpha_node_kernel<<<NN, 128>>>(be + l * DD);
        gather_kernel    <<<NN, 128>>>(be + l * DD);

        bn_sum_kernel  <<<256, 128>>>();
        bn_fin_kernel  <<<1, 128>>>(gamma + l * DD, beta + l * DD);
        bn_apply_kernel<<<(NN * DD + 255) / 256, 256>>>(out, (l == LL - 1) ? 1 : 0);
    }
}

// round 11
// speedup vs baseline: 2.3197x; 2.3197x over previous
#include <cuda_runtime.h>
#include <cuda_fp16.h>
#include <cstdint>

// Problem constants (fixed by the reference)
#define NN   50000
#define EE   800000
#define DD   128
#define HH   8
#define CC   16
#define EDD  64
#define LL   3

// ---------------- scratch (static device globals; no allocation) -------------
__device__ float  g_q  [NN * DD];
__device__ float  g_k  [NN * DD];
__device__ float  g_v  [NN * DD];
__device__ float  g_out[NN * DD];     // skip (x@Ws+bs), then final pre-BN out
__device__ __half g_xh [NN * DD];     // x split hi
__device__ __half g_xl [NN * DD];     // x split lo
__device__ __half g_e  [(size_t)EE * DD];      // per-edge e (fp16, CSR order)
__device__ __half g_ea16[(size_t)EE * EDD];    // edge_attr fp16, CSR-permuted
__device__ __half g_wet [DD * EDD];            // We^T fp16 [n=128][k=64]
__device__ __half g_wallh[512 * DD];           // [Wq|Wk|Wv|Ws]^T hi
__device__ __half g_walll[512 * DD];           // lo part
__device__ float  g_ball [512];                // [bq|bk|bv|bs]
__device__ float  g_alpha[(size_t)EE * HH];    // raw scores (CSR order)
__device__ double g_sums[2 * DD];
__device__ float2 g_ab  [DD];
// CSR (dst-sorted edge order; edge_index is launch-constant)
__device__ int    g_deg   [NN];
__device__ int    g_cursor[NN];
__device__ int    g_rowptr[NN + 1];
__device__ int    g_eord  [EE];
__device__ int    g_srcp  [EE];      // src per CSR position
__device__ int    g_dstp  [EE];      // dst per CSR position
__device__ int    g_bsums [256];

// ---------------- helpers ----------------------------------------------------
__device__ __forceinline__ uint32_t smem_u32(const void* p) {
    uint32_t a;
    asm("{ .reg .u64 t; cvta.to.shared.u64 t, %1; cvt.u32.u64 %0, t; }" : "=r"(a) : "l"(p));
    return a;
}
__device__ __forceinline__ uint32_t sw128(uint32_t off) { return off ^ ((off >> 3) & 0x70); }
__device__ __forceinline__ uint32_t sw64 (uint32_t off) { return off ^ ((off >> 3) & 0x30); }

__device__ __forceinline__ void ldmatrix_x4(uint32_t* r, uint32_t addr) {
    asm volatile("ldmatrix.sync.aligned.m8n8.x4.shared.b16 {%0,%1,%2,%3}, [%4];"
                 : "=r"(r[0]), "=r"(r[1]), "=r"(r[2]), "=r"(r[3]) : "r"(addr));
}
__device__ __forceinline__ void mma16816(float* c, const uint32_t* a, const uint32_t* b) {
    asm volatile("mma.sync.aligned.m16n8k16.row.col.f32.f16.f16.f32 "
                 "{%0,%1,%2,%3}, {%4,%5,%6,%7}, {%8,%9}, {%0,%1,%2,%3};"
                 : "+f"(c[0]), "+f"(c[1]), "+f"(c[2]), "+f"(c[3])
                 : "r"(a[0]), "r"(a[1]), "r"(a[2]), "r"(a[3]), "r"(b[0]), "r"(b[1]));
}

// ---------------- CSR build (once per launch) ----------------------------------
__global__ void csr_zero() {
    int i = blockIdx.x * blockDim.x + threadIdx.x;
    if (i < NN) { g_deg[i] = 0; g_cursor[i] = 0; }
}
__global__ void csr_hist(const int* __restrict__ ei) {
    int e = blockIdx.x * blockDim.x + threadIdx.x;
    if (e < EE) atomicAdd(&g_deg[ei[EE + e]], 1);
}
__global__ void csr_scan1() {
    __shared__ int s[256];
    int t = threadIdx.x;
    int i = blockIdx.x * 256 + t;
    int v = (i < NN) ? g_deg[i] : 0;
    s[t] = v;
    __syncthreads();
    for (int st = 1; st < 256; st <<= 1) {
        int x = (t >= st) ? s[t - st] : 0;
        __syncthreads();
        if (t >= st) s[t] += x;
        __syncthreads();
    }
    if (i < NN) g_rowptr[i] = s[t] - v;
    if (t == 255) g_bsums[blockIdx.x] = s[255];
}
__global__ void csr_scan2(int nblocks) {      // parallel exclusive scan of block sums
    __shared__ int s[256];
    int t = threadIdx.x;
    int v = (t < nblocks) ? g_bsums[t] : 0;
    s[t] = v;
    __syncthreads();
    for (int st = 1; st < 256; st <<= 1) {
        int x = (t >= st) ? s[t - st] : 0;
        __syncthreads();
        if (t >= st) s[t] += x;
        __syncthreads();
    }
    if (t < nblocks) g_bsums[t] = s[t] - v;
}
__global__ void csr_scan3() {
    int i = blockIdx.x * blockDim.x + threadIdx.x;
    if (i < NN) g_rowptr[i] += g_bsums[i >> 8];
    if (i == 0) g_rowptr[NN] = EE;
}
__global__ void csr_fill(const int* __restrict__ ei) {
    int e = blockIdx.x * blockDim.x + threadIdx.x;
    if (e >= EE) return;
    int d = ei[EE + e];
    int pos = g_rowptr[d] + atomicAdd(&g_cursor[d], 1);
    g_eord[pos] = e;
}
__global__ void perm_idx_kernel(const int* __restrict__ ei) {
    int p = blockIdx.x * blockDim.x + threadIdx.x;
    if (p >= EE) return;
    int eid = g_eord[p];
    g_srcp[p] = ei[eid];
    g_dstp[p] = ei[EE + eid];
}
// edge_attr -> fp16, permuted into CSR order
__global__ void conv_ea_perm(const float* __restrict__ ea) {
    int i = blockIdx.x * blockDim.x + threadIdx.x;   // over 4-float units
    int p = i >> 4;
    if (p >= EE) return;
    int off = (i & 15) * 4;
    int eid = g_eord[p];
    float4 f = *(const float4*)(ea + (size_t)eid * EDD + off);
    __half2 h01 = __floats2half2_rn(f.x, f.y);
    __half2 h23 = __floats2half2_rn(f.z, f.w);
    uint2 pk;
    pk.x = *(const unsigned*)&h01;
    pk.y = *(const unsigned*)&h23;
    *(uint2*)(g_ea16 + (size_t)p * EDD + off) = pk;
}

// ---------------- one-time / per-layer prep ------------------------------------
__global__ void xsplit0_kernel(const float* __restrict__ x) {
    int i = blockIdx.x * blockDim.x + threadIdx.x;
    if (i >= NN * DD) return;
    float f = x[i];
    __half h = __float2half(f);
    g_xh[i] = h;
    g_xl[i] = __float2half(f - __half2float(h));
}

__global__ void wet_kernel(const float* __restrict__ We) {
    int i = blockIdx.x * blockDim.x + threadIdx.x;
    if (i >= DD * EDD) return;
    int n = i / EDD, k = i % EDD;
    g_wet[i] = __float2half(We[k * DD + n]);
}

__global__ void wall_prep_kernel(const float* __restrict__ Wq, const float* __restrict__ Wk,
                                 const float* __restrict__ Wv, const float* __restrict__ Ws,
                                 const float* __restrict__ bq, const float* __restrict__ bk,
                                 const float* __restrict__ bv, const float* __restrict__ bs) {
    int i = blockIdx.x * blockDim.x + threadIdx.x;
    if (i >= 512 * DD) return;
    int ng = i / DD;
    int k  = i % DD;
    int mtx = ng >> 7, nloc = ng & 127;
    const float* W = (mtx == 0) ? Wq : (mtx == 1) ? Wk : (mtx == 2) ? Wv : Ws;
    float w = W[k * DD + nloc];
    __half h = __float2half(w);
    g_wallh[i] = h;
    g_walll[i] = __float2half(w - __half2float(h));
    if (i < 512) {
        int m2 = i >> 7, l2 = i & 127;
        const float* b = (m2 == 0) ? bq : (m2 == 1) ? bk : (m2 == 2) ? bv : bs;
        g_ball[i] = b[l2];
    }
}

__global__ void init_kernel() {
    int i = threadIdx.x;
    if (i < 2 * DD) g_sums[i] = 0.0;
}

// ------------- fused node GEMM (split-fp16 HMMA): [q|k|v|skip] -----------------
__global__ void __launch_bounds__(256, 2)
node_gemm_mma(float* __restrict__ oq, float* __restrict__ okk,
              float* __restrict__ ov, float* __restrict__ os) {
    __shared__ __align__(128) __half sAh[128 * 32];
    __shared__ __align__(128) __half sAl[128 * 32];
    __shared__ __align__(128) __half sBh[128 * 32];
    __shared__ __align__(128) __half sBl[128 * 32];
    __shared__ float sbias[128];

    const int tid  = threadIdx.x;
    const int wid  = tid >> 5;
    const int lane = tid & 31;
    const int ntile = blockIdx.x & 3;
    const int mbase = (blockIdx.x >> 2) * 128;

    if (tid < 128) sbias[tid] = g_ball[ntile * 128 + tid];

    float acc[16][4];
#pragma unroll
    for (int i = 0; i < 16; i++)
#pragma unroll
        for (int j = 0; j < 4; j++) acc[i][j] = 0.0f;

    const uint32_t sAhu = smem_u32(sAh);
    const uint32_t sAlu = smem_u32(sAl);
    const uint32_t sBhu = smem_u32(sBh);
    const uint32_t sBlu = smem_u32(sBl);
    const int mrow = wid * 16;

    for (int kc = 0; kc < 4; kc++) {
#pragma unroll
        for (int i = 0; i < 2; i++) {
            int idx = i * 256 + tid;
            int row = idx >> 2, unit = idx & 3;
            int grow = mbase + row;
            uint4 vh = make_uint4(0, 0, 0, 0), vl = make_uint4(0, 0, 0, 0);
            if (grow < NN) {
                size_t g = (size_t)grow * DD + kc * 32 + unit * 8;
                vh = *(const uint4*)(g_xh + g);
                vl = *(const uint4*)(g_xl + g);
            }
            *(uint4*)((char*)sAh + sw64(idx * 16)) = vh;
            *(uint4*)((char*)sAl + sw64(idx * 16)) = vl;
        }
#pragma unroll
        for (int i = 0; i < 2; i++) {
            int idx = i * 256 + tid;
            int row = idx >> 2, unit = idx & 3;
            size_t g = (size_t)(ntile * 128 + row) * DD + kc * 32 + unit * 8;
            *(uint4*)((char*)sBh + sw64(idx * 16)) = *(const uint4*)(g_wallh + g);
            *(uint4*)((char*)sBl + sw64(idx * 16)) = *(const uint4*)(g_walll + g);
        }
        __syncthreads();

#pragma unroll
        for (int t = 0; t < 2; t++) {
            uint32_t ah[4], al[4];
            uint32_t aoff = (uint32_t)(mrow + (lane & 15)) * 64 + t * 32 + ((lane >> 4) * 16);
            ldmatrix_x4(ah, sAhu + sw64(aoff));
            ldmatrix_x4(al, sAlu + sw64(aoff));
#pragma unroll
            for (int np = 0; np < 8; np++) {
                int mtx = lane >> 3;
                uint32_t boff = (uint32_t)(np * 16 + ((mtx >> 1) * 8) + (lane & 7)) * 64
                              + t * 32 + ((mtx & 1) * 16);
                uint32_t bh[4], bl[4];
                ldmatrix_x4(bh, sBhu + sw64(boff));
                ldmatrix_x4(bl, sBlu + sw64(boff));
                mma16816(acc[2 * np],     ah, bh);
                mma16816(acc[2 * np],     ah, bl);
                mma16816(acc[2 * np],     al, bh);
                mma16816(acc[2 * np + 1], ah, bh + 2);
                mma16816(acc[2 * np + 1], ah, bl + 2);
                mma16816(acc[2 * np + 1], al, bh + 2);
            }
        }
        __syncthreads();
    }

    float* dst = (ntile == 0) ? oq : (ntile == 1) ? okk : (ntile == 2) ? ov : os;
    const int r0 = mbase + mrow + (lane >> 2);
    const int cq = (lane & 3) * 2;
#pragma unroll
    for (int nt = 0; nt < 16; nt++) {
        int n = nt * 8 + cq;
        float b0 = sbias[n], b1 = sbias[n + 1];
        if (r0 < NN)
            *(float2*)(dst + (size_t)r0 * DD + n) = make_float2(acc[nt][0] + b0, acc[nt][1] + b1);
        if (r0 + 8 < NN)
            *(float2*)(dst + (size_t)(r0 + 8) * DD + n) = make_float2(acc[nt][2] + b0, acc[nt][3] + b1);
    }
}

// -------- edge GEMM (CSR order) + e store + fused alpha -------------------------
__global__ void __launch_bounds__(256, 2)
edge_gemm_mma(const float* __restrict__ bias) {
    __shared__ __align__(128) __half sA[128 * 64];
    __shared__ __align__(128) __half sB[128 * 64];
    __shared__ float sbias[128];

    const int tid  = threadIdx.x;
    const int wid  = tid >> 5;
    const int lane = tid & 31;
    const size_t tile = blockIdx.x;

    if (tid < 128) sbias[tid] = bias[tid];

    const uint4* Ag = (const uint4*)(g_ea16 + tile * 128 * EDD);
#pragma unroll
    for (int i = 0; i < 4; i++) {
        int idx = i * 256 + tid;
        uint4 val = Ag[idx];
        *(uint4*)((char*)sA + sw128(idx * 16)) = val;
    }
    const uint4* Bg = (const uint4*)g_wet;
#pragma unroll
    for (int i = 0; i < 4; i++) {
        int idx = i * 256 + tid;
        uint4 val = Bg[idx];
        *(uint4*)((char*)sB + sw128(idx * 16)) = val;
    }
    __syncthreads();

    const uint32_t sAu = smem_u32(sA);
    const uint32_t sBu = smem_u32(sB);
    const int mrow = wid * 16;

    uint32_t afrag[4][4];
#pragma unroll
    for (int t = 0; t < 4; t++) {
        uint32_t off = (uint32_t)(mrow + (lane & 15)) * 128 + t * 32 + ((lane >> 4) * 16);
        ldmatrix_x4(afrag[t], sAu + sw128(off));
    }

    float acc[16][4];
#pragma unroll
    for (int i = 0; i < 16; i++)
#pragma unroll
        for (int j = 0; j < 4; j++) acc[i][j] = 0.0f;

#pragma unroll
    for (int t = 0; t < 4; t++) {
#pragma unroll
        for (int np = 0; np < 8; np++) {
            int mtx = lane >> 3;
            int n   = np * 16 + ((mtx >> 1) * 8) + (lane & 7);
            int kb  = t * 32 + ((mtx & 1) * 16);
            uint32_t b[4];
            ldmatrix_x4(b, sBu + sw128((uint32_t)n * 128 + kb));
            mma16816(acc[2 * np],     afrag[t], b);
            mma16816(acc[2 * np + 1], afrag[t], b + 2);
        }
    }

    const int p0 = (int)tile * 128 + mrow + (lane >> 2);
    const int p1 = p0 + 8;
    const int cq = (lane & 3) * 2;
    const int src0 = g_srcp[p0], dst0 = g_dstp[p0];
    const int src1 = g_srcp[p1], dst1 = g_dstp[p1];
    const float* q0 = g_q + (size_t)dst0 * DD;
    const float* k0 = g_k + (size_t)src0 * DD;
    const float* q1 = g_q + (size_t)dst1 * DD;
    const float* k1 = g_k + (size_t)src1 * DD;
    __half* e0p = g_e + (size_t)p0 * DD;
    __half* e1p = g_e + (size_t)p1 * DD;

    float ps0[8], ps1[8];
#pragma unroll
    for (int h = 0; h < 8; h++) { ps0[h] = 0.0f; ps1[h] = 0.0f; }

#pragma unroll
    for (int nt = 0; nt < 16; nt++) {
        int n = nt * 8 + cq;
        int h = nt >> 1;
        float b0 = sbias[n], b1 = sbias[n + 1];
        float ea0 = acc[nt][0] + b0, ea1 = acc[nt][1] + b1;
        float eb0 = acc[nt][2] + b0, eb1 = acc[nt][3] + b1;
        *(__half2*)(e0p + n) = __floats2half2_rn(ea0, ea1);
        *(__half2*)(e1p + n) = __floats2half2_rn(eb0, eb1);
        float2 qa = *(const float2*)(q0 + n);
        float2 ka = *(const float2*)(k0 + n);
        float2 qb = *(const float2*)(q1 + n);
        float2 kb = *(const float2*)(k1 + n);
        ps0[h] += qa.x * (ka.x + ea0) + qa.y * (ka.y + ea1);
        ps1[h] += qb.x * (kb.x + eb0) + qb.y * (kb.y + eb1);
    }
#pragma unroll
    for (int h = 0; h < 8; h++) {
        ps0[h] += __shfl_xor_sync(0xFFFFFFFFu, ps0[h], 1);
        ps0[h] += __shfl_xor_sync(0xFFFFFFFFu, ps0[h], 2);
        ps1[h] += __shfl_xor_sync(0xFFFFFFFFu, ps1[h], 1);
        ps1[h] += __shfl_xor_sync(0xFFFFFFFFu, ps1[h], 2);
    }
    const int qid = lane & 3;
#pragma unroll
    for (int h = 0; h < 8; h++) {
        if ((h & 3) == qid) {
            g_alpha[(size_t)p0 * HH + h] = ps0[h] * 0.25f;
            g_alpha[(size_t)p1 * HH + h] = ps1[h] * 0.25f;
        }
    }
}

// ------------- per-node gather: softmax + message sum + skip add ---------------
// alpha/e sequential (CSR order); v gathered (L2-resident). All chunk data staged
// into smem with uint4 loads to cut LSU instruction count 4-8x.
__global__ void __launch_bounds__(128)
gather_kernel() {
    const int n   = blockIdx.x;
    const int tid = threadIdx.x;
    const int start = g_rowptr[n], end = g_rowptr[n + 1];
    const int i0 = tid >> 3, h8 = tid & 7;
    const int hch = tid >> 4;

    __shared__ float smax[128];
    __shared__ float sex[16][8];
    __shared__ int   ssrc[16];
    __shared__ float sden[8];
    __shared__ __align__(16) float  sV[16 * 128];   // 8 KB
    __shared__ __align__(16) __half sE[16 * 128];   // 4 KB

    float lmax = -3.0e38f;
    for (int p = start + i0; p < end; p += 16)
        lmax = fmaxf(lmax, g_alpha[(size_t)p * HH + h8]);
    smax[tid] = lmax;
    __syncthreads();
#pragma unroll
    for (int s = 64; s >= 8; s >>= 1) {
        if (tid < s) smax[tid] = fmaxf(smax[tid], smax[tid + s]);
        __syncthreads();
    }
    const float amax = smax[h8];

    float msg = 0.0f, den = 0.0f;
    for (int base = start; base < end; base += 16) {
        int cnt = min(16, end - base);
        if (tid < cnt) ssrc[tid] = g_srcp[base + tid];
        if (i0 < cnt)
            sex[i0][h8] = __expf(g_alpha[(size_t)(base + i0) * HH + h8] - amax);
        __syncthreads();   // ssrc ready

        // stage e rows: cnt*16 uint4, fully linear from g_e + base*DD
        {
            const uint4* src = (const uint4*)(g_e + (size_t)base * DD);
            uint4* dst = (uint4*)sE;
            for (int u = tid; u < cnt * 16; u += 128) dst[u] = src[u];
        }
        // stage v rows: cnt*32 uint4, gathered per row
        {
            uint4* dst = (uint4*)sV;
            for (int u = tid; u < cnt * 32; u += 128) {
                int row = u >> 5, c = u & 31;
                dst[u] = ((const uint4*)(g_v + (size_t)ssrc[row] * DD))[c];
            }
        }
        __syncthreads();   // staged data ready

#pragma unroll 4
        for (int i = 0; i < cnt; i++) {
            float ex = sex[i][hch];
            msg += (sV[i * 128 + tid] + __half2float(sE[i * 128 + tid])) * ex;
        }
        if (tid < 8) {
            float s = 0.0f;
            for (int i = 0; i < cnt; i++) s += sex[i][tid];
            den += s;
        }
        __syncthreads();   // protect sex/ssrc for next chunk
    }
    if (tid < 8) sden[tid] = den;
    __syncthreads();

    float o = msg / (sden[hch] + 1e-16f) + g_out[(size_t)n * DD + tid];
    g_out[(size_t)n * DD + tid] = o;
}

// ---- BN column sums (fp64) -----------------------------------------------------
__global__ void bn_sum_kernel() {
    int ch = threadIdx.x;
    double s = 0.0, s2 = 0.0;
    for (int r = blockIdx.x; r < NN; r += gridDim.x) {
        float v = g_out[(size_t)r * DD + ch];
        s  += (double)v;
        s2 += (double)v * (double)v;
    }
    atomicAdd(&g_sums[ch], s);
    atomicAdd(&g_sums[DD + ch], s2);
}

__global__ void bn_fin_kernel(const float* __restrict__ gamma,
                              const float* __restrict__ beta) {
    int ch = threadIdx.x;
    double mu  = g_sums[ch] / (double)NN;
    double var = g_sums[DD + ch] / (double)NN - mu * mu;
    double rs  = 1.0 / sqrt(var + 1e-5);
    float a = gamma[ch] * (float)rs;
    float b = beta[ch] - (float)mu * a;
    g_ab[ch] = make_float2(a, b);
}

__global__ void bn_apply_kernel(float* __restrict__ xo, int write_f32) {
    int idx = blockIdx.x * blockDim.x + threadIdx.x;
    if (idx >= NN * DD) return;
    int ch = idx & (DD - 1);
    float2 c = g_ab[ch];
    float y = g_out[idx] * c.x + c.y;
    y = (y >= 0.0f) ? y : 0.01f * y;
    __half h = __float2half(y);
    g_xh[idx] = h;
    g_xl[idx] = __float2half(y - __half2float(h));
    if (write_f32) xo[idx] = y;
}

// ---------------- driver -------------------------------------------------------
extern "C" void kernel_launch(void* const* d_in, const int* in_sizes, int n_in,
                              void* d_out, int out_size) {
    const float* x     = (const float*)d_in[0];
    const int*   ei    = (const int*)  d_in[1];
    const float* ea    = (const float*)d_in[2];
    const float* Wq    = (const float*)d_in[3];
    const float* bq    = (const float*)d_in[4];
    const float* Wk    = (const float*)d_in[5];
    const float* bk    = (const float*)d_in[6];
    const float* Wv    = (const float*)d_in[7];
    const float* bv    = (const float*)d_in[8];
    const float* We    = (const float*)d_in[9];
    const float* be    = (const float*)d_in[10];
    const float* Ws    = (const float*)d_in[11];
    const float* bs    = (const float*)d_in[12];
    const float* gamma = (const float*)d_in[13];
    const float* beta  = (const float*)d_in[14];
    float* out = (float*)d_out;

    float *q, *k, *v, *ob;
    cudaGetSymbolAddress((void**)&q,  g_q);
    cudaGetSymbolAddress((void**)&k,  g_k);
    cudaGetSymbolAddress((void**)&v,  g_v);
    cudaGetSymbolAddress((void**)&ob, g_out);

    const int edgeTiles      = EE / 128;                // 6250
    const int nodeGemmBlocks = ((NN + 127) / 128) * 4;  // 1564
    const int nodeB          = (NN + 255) / 256;        // 196

    // one-time per launch: CSR build, permutation, conversions
    csr_zero <<<nodeB, 256>>>();
    csr_hist <<<(EE + 255) / 256, 256>>>(ei);
    csr_scan1<<<nodeB, 256>>>();
    csr_scan2<<<1, 256>>>(nodeB);
    csr_scan3<<<nodeB, 256>>>();
    csr_fill <<<(EE + 255) / 256, 256>>>(ei);
    perm_idx_kernel<<<(EE + 255) / 256, 256>>>(ei);
    conv_ea_perm<<<(int)(((size_t)EE * 16 + 255) / 256), 256>>>(ea);
    xsplit0_kernel<<<(NN * DD + 255) / 256, 256>>>(x);

    for (int l = 0; l < LL; l++) {
        init_kernel<<<1, 256>>>();
        wet_kernel <<<(DD * EDD + 255) / 256, 256>>>(We + (size_t)l * EDD * DD);
        wall_prep_kernel<<<(512 * DD + 255) / 256, 256>>>(
            Wq + (size_t)l * DD * DD, Wk + (size_t)l * DD * DD,
            Wv + (size_t)l * DD * DD, Ws + (size_t)l * DD * DD,
            bq + l * DD, bk + l * DD, bv + l * DD, bs + l * DD);

        node_gemm_mma<<<nodeGemmBlocks, 256>>>(q, k, v, ob);

        edge_gemm_mma<<<edgeTiles, 256>>>(be + l * DD);

        gather_kernel<<<NN, 128>>>();

        bn_sum_kernel  <<<256, 128>>>();
        bn_fin_kernel  <<<1, 128>>>(gamma + l * DD, beta + l * DD);
        bn_apply_kernel<<<(NN * DD + 255) / 256, 256>>>(out, (l == LL - 1) ? 1 : 0);
    }
}